// round 4
// baseline (speedup 1.0000x reference)
#include <cuda_runtime.h>
#include <cstdint>

#define N_NODES 100000
#define E_EDGES 1600000
#define IN_F    256
#define OUT_F   128

// ---------------- device scratch (no runtime allocation allowed) ----------
__device__ float        g_proj[(size_t)N_NODES * OUT_F];   // projected feats [N, OUT]
__device__ float        g_w[IN_F * OUT_F];                  // masked weight
__device__ float        g_inv_out[N_NODES];
__device__ float        g_inv_in[N_NODES];
__device__ unsigned int g_outdeg[N_NODES];
__device__ unsigned int g_indeg[N_NODES];

// ---------------- kernel 1: zero output + degree counters -----------------
__global__ void zero_kernel(float* __restrict__ out) {
    int i = blockIdx.x * blockDim.x + threadIdx.x;
    int n4 = (N_NODES * OUT_F) / 4;
    if (i < n4) {
        reinterpret_cast<float4*>(out)[i] = make_float4(0.f, 0.f, 0.f, 0.f);
    }
    if (i < N_NODES) {
        g_outdeg[i] = 0u;
        g_indeg[i]  = 0u;
    }
}

// ---------------- kernel 2: count degrees ---------------------------------
__global__ void count_kernel(const int* __restrict__ src, const int* __restrict__ dst) {
    int e = blockIdx.x * blockDim.x + threadIdx.x;
    if (e >= E_EDGES) return;
    atomicAdd(&g_outdeg[src[e]], 1u);
    atomicAdd(&g_indeg[dst[e]], 1u);
}

// ---------------- kernel 3: masked weight ---------------------------------
__global__ void maskw_kernel(const float* __restrict__ weight,
                             const float* __restrict__ mask_real) {
    int i = blockIdx.x * blockDim.x + threadIdx.x;
    if (i >= IN_F * OUT_F) return;
    g_w[i] = (mask_real[i] > 0.5f) ? weight[i] : 0.0f;
}

// ---------------- kernel 4: inverse sqrt degrees ---------------------------
__global__ void invdeg_kernel() {
    int i = blockIdx.x * blockDim.x + threadIdx.x;
    if (i >= N_NODES) return;
    float od = fmaxf((float)g_outdeg[i], 1.0f);
    float id = fmaxf((float)g_indeg[i], 1.0f);
    g_inv_out[i] = rsqrtf(od);
    g_inv_in[i]  = rsqrtf(id);
}

// ---------------- kernel 5: SGEMM  g_proj = (feat * inv_out) @ g_w ---------
// Block tile: 128 rows x 128 cols, BK=16, 256 threads, 8x8 register tile.
#define BM 128
#define BN 128
#define BK 16

__global__ __launch_bounds__(256, 1)
void gemm_kernel(const float* __restrict__ feat) {
    __shared__ float As[BK][BM];   // transposed A tile (scaled)
    __shared__ float Bs[BK][BN];

    const int tid = threadIdx.x;
    const int tx  = tid & 15;         // 0..15 -> col group
    const int ty  = tid >> 4;         // 0..15 -> row group
    const int block_row = blockIdx.x * BM;

    // A-load mapping: 2 threads per row, 8 consecutive k each
    const int row_a = tid >> 1;                 // 0..127
    const int ka    = (tid & 1) * 8;            // 0 or 8
    const int grow  = block_row + row_a;
    const bool row_ok = (grow < N_NODES);
    const float scale = row_ok ? g_inv_out[grow] : 0.0f;

    // B-load mapping: row kb = tid/16, cols (tid%16)*8
    const int kb = tid >> 4;                    // 0..15
    const int cb = (tid & 15) * 8;              // 0..120

    float acc[8][8];
#pragma unroll
    for (int i = 0; i < 8; ++i)
#pragma unroll
        for (int j = 0; j < 8; ++j) acc[i][j] = 0.0f;

    for (int k0 = 0; k0 < IN_F; k0 += BK) {
        // --- load A tile (scaled, transposed into As) ---
        float4 a0 = make_float4(0.f,0.f,0.f,0.f);
        float4 a1 = a0;
        if (row_ok) {
            const float4* fp = reinterpret_cast<const float4*>(
                feat + (size_t)grow * IN_F + k0 + ka);
            a0 = fp[0];
            a1 = fp[1];
        }
        As[ka + 0][row_a] = a0.x * scale;
        As[ka + 1][row_a] = a0.y * scale;
        As[ka + 2][row_a] = a0.z * scale;
        As[ka + 3][row_a] = a0.w * scale;
        As[ka + 4][row_a] = a1.x * scale;
        As[ka + 5][row_a] = a1.y * scale;
        As[ka + 6][row_a] = a1.z * scale;
        As[ka + 7][row_a] = a1.w * scale;

        // --- load B tile ---
        const float4* wp = reinterpret_cast<const float4*>(
            g_w + (size_t)(k0 + kb) * OUT_F + cb);
        float4 b0 = wp[0];
        float4 b1 = wp[1];
        *reinterpret_cast<float4*>(&Bs[kb][cb])     = b0;
        *reinterpret_cast<float4*>(&Bs[kb][cb + 4]) = b1;

        __syncthreads();

#pragma unroll
        for (int k = 0; k < BK; ++k) {
            float4 ar0 = *reinterpret_cast<const float4*>(&As[k][ty * 8]);
            float4 ar1 = *reinterpret_cast<const float4*>(&As[k][ty * 8 + 4]);
            float4 br0 = *reinterpret_cast<const float4*>(&Bs[k][tx * 8]);
            float4 br1 = *reinterpret_cast<const float4*>(&Bs[k][tx * 8 + 4]);
            float ar[8] = {ar0.x, ar0.y, ar0.z, ar0.w, ar1.x, ar1.y, ar1.z, ar1.w};
            float br[8] = {br0.x, br0.y, br0.z, br0.w, br1.x, br1.y, br1.z, br1.w};
#pragma unroll
            for (int i = 0; i < 8; ++i)
#pragma unroll
                for (int j = 0; j < 8; ++j)
                    acc[i][j] = fmaf(ar[i], br[j], acc[i][j]);
        }
        __syncthreads();
    }

    // --- store ---
#pragma unroll
    for (int i = 0; i < 8; ++i) {
        int r = block_row + ty * 8 + i;
        if (r >= N_NODES) continue;
        float4 o0 = make_float4(acc[i][0], acc[i][1], acc[i][2], acc[i][3]);
        float4 o1 = make_float4(acc[i][4], acc[i][5], acc[i][6], acc[i][7]);
        float* op = g_proj + (size_t)r * OUT_F + tx * 8;
        *reinterpret_cast<float4*>(op)     = o0;
        *reinterpret_cast<float4*>(op + 4) = o1;
    }
}

// ---------------- kernel 6: edge gather + scatter-add ----------------------
// One warp per edge. Each lane handles one float4 (128 floats / 32 lanes).
__global__ __launch_bounds__(256)
void edge_kernel(const int* __restrict__ src, const int* __restrict__ dst,
                 const float* __restrict__ ew, float* __restrict__ out) {
    int warp = (blockIdx.x * blockDim.x + threadIdx.x) >> 5;
    int lane = threadIdx.x & 31;
    if (warp >= E_EDGES) return;

    int   s = src[warp];
    int   d = dst[warp];
    float w = ew[warp];

    const float4* fp = reinterpret_cast<const float4*>(g_proj + (size_t)s * OUT_F);
    float4 v = fp[lane];
    v.x *= w; v.y *= w; v.z *= w; v.w *= w;

    float* addr = out + (size_t)d * OUT_F + lane * 4;
    asm volatile("red.global.add.v4.f32 [%0], {%1, %2, %3, %4};"
                 :: "l"(addr), "f"(v.x), "f"(v.y), "f"(v.z), "f"(v.w)
                 : "memory");
}

// ---------------- kernel 7: finalize (in-deg norm + bias) ------------------
__global__ void finalize_kernel(float* __restrict__ out, const float* __restrict__ bias) {
    int i = blockIdx.x * blockDim.x + threadIdx.x;
    int n4 = (N_NODES * OUT_F) / 4;
    if (i >= n4) return;
    int row = i / (OUT_F / 4);
    int c4  = i % (OUT_F / 4);
    float s = g_inv_in[row];
    float4 v = reinterpret_cast<float4*>(out)[i];
    float4 b = reinterpret_cast<const float4*>(bias)[c4];
    v.x = fmaf(v.x, s, b.x);
    v.y = fmaf(v.y, s, b.y);
    v.z = fmaf(v.z, s, b.z);
    v.w = fmaf(v.w, s, b.w);
    reinterpret_cast<float4*>(out)[i] = v;
}

// ---------------- launch ----------------------------------------------------
extern "C" void kernel_launch(void* const* d_in, const int* in_sizes, int n_in,
                              void* d_out, int out_size) {
    const float* feat      = (const float*)d_in[0];
    const int*   src       = (const int*)  d_in[1];
    const int*   dst       = (const int*)  d_in[2];
    const float* ew        = (const float*)d_in[3];
    const float* weight    = (const float*)d_in[4];
    const float* bias      = (const float*)d_in[5];
    const float* mask_real = (const float*)d_in[6];
    float* out = (float*)d_out;

    const int n4 = (N_NODES * OUT_F) / 4;   // 3.2M float4s

    zero_kernel<<<(n4 + 255) / 256, 256>>>(out);
    count_kernel<<<(E_EDGES + 255) / 256, 256>>>(src, dst);
    maskw_kernel<<<(IN_F * OUT_F + 255) / 256, 256>>>(weight, mask_real);
    invdeg_kernel<<<(N_NODES + 255) / 256, 256>>>();
    gemm_kernel<<<(N_NODES + BM - 1) / BM, 256>>>(feat);
    edge_kernel<<<E_EDGES / 8, 256>>>(src, dst, ew, out);   // 8 warps/block, 1 edge/warp
    finalize_kernel<<<(n4 + 255) / 256, 256>>>(out, bias);
}

// round 5
// speedup vs baseline: 1.3250x; 1.3250x over previous
#include <cuda_runtime.h>
#include <cstdint>

#define N_NODES 100000
#define E_EDGES 1600000
#define IN_F    256
#define OUT_F   128

// ---------------- device scratch (no runtime allocation allowed) ----------
__device__ float        g_proj[(size_t)N_NODES * OUT_F];   // projected feats [N, OUT]
__device__ float        g_w[IN_F * OUT_F];                  // masked weight
__device__ float        g_inv_out[N_NODES];
__device__ float        g_inv_in[N_NODES];
__device__ unsigned int g_outdeg[N_NODES];
__device__ unsigned int g_indeg[N_NODES];
// CSR-by-dst scratch
__device__ int          g_start[N_NODES];     // exclusive prefix of indeg
__device__ int          g_cur[N_NODES];       // scatter cursors
__device__ int          g_bsum[512];          // block sums for scan
__device__ int          g_esrc[E_EDGES];      // src per CSR slot
__device__ float        g_eww[E_EDGES];       // edge weight per CSR slot

// ---------------- kernel 1: zero degree counters ---------------------------
__global__ void zerodeg_kernel() {
    int i = blockIdx.x * blockDim.x + threadIdx.x;
    if (i < N_NODES) {
        g_outdeg[i] = 0u;
        g_indeg[i]  = 0u;
    }
}

// ---------------- kernel 2: count degrees ---------------------------------
__global__ void count_kernel(const int* __restrict__ src, const int* __restrict__ dst) {
    int e = blockIdx.x * blockDim.x + threadIdx.x;
    if (e >= E_EDGES) return;
    atomicAdd(&g_outdeg[src[e]], 1u);
    atomicAdd(&g_indeg[dst[e]], 1u);
}

// ---------------- kernel 3: masked weight ---------------------------------
__global__ void maskw_kernel(const float* __restrict__ weight,
                             const float* __restrict__ mask_real) {
    int i = blockIdx.x * blockDim.x + threadIdx.x;
    if (i >= IN_F * OUT_F) return;
    g_w[i] = (mask_real[i] > 0.5f) ? weight[i] : 0.0f;
}

// ---------------- kernel 4: inverse sqrt degrees ---------------------------
__global__ void invdeg_kernel() {
    int i = blockIdx.x * blockDim.x + threadIdx.x;
    if (i >= N_NODES) return;
    float od = fmaxf((float)g_outdeg[i], 1.0f);
    float id = fmaxf((float)g_indeg[i], 1.0f);
    g_inv_out[i] = rsqrtf(od);
    g_inv_in[i]  = rsqrtf(id);
}

// ---------------- scan kernels: exclusive prefix sum of indeg --------------
__global__ void scanA_kernel() {
    __shared__ int s[256];
    int t = threadIdx.x;
    int i = blockIdx.x * 256 + t;
    int v = (i < N_NODES) ? (int)g_indeg[i] : 0;
    s[t] = v;
    __syncthreads();
#pragma unroll
    for (int off = 1; off < 256; off <<= 1) {
        int add = (t >= off) ? s[t - off] : 0;
        __syncthreads();
        s[t] += add;
        __syncthreads();
    }
    if (i < N_NODES) g_start[i] = s[t] - v;   // exclusive within block
    if (t == 255) g_bsum[blockIdx.x] = s[255];
}

__global__ void scanB_kernel(int nblocks) {
    __shared__ int s[512];
    int t = threadIdx.x;
    int v = (t < nblocks) ? g_bsum[t] : 0;
    s[t] = v;
    __syncthreads();
#pragma unroll
    for (int off = 1; off < 512; off <<= 1) {
        int add = (t >= off) ? s[t - off] : 0;
        __syncthreads();
        s[t] += add;
        __syncthreads();
    }
    if (t < nblocks) g_bsum[t] = s[t] - v;    // exclusive
}

__global__ void scanC_kernel() {
    int i = blockIdx.x * blockDim.x + threadIdx.x;
    if (i >= N_NODES) return;
    int st = g_start[i] + g_bsum[blockIdx.x * 256 / 256 == 0 ? 0 : 0];
    // (recompute properly: block index of element i in scanA == i/256)
    st = g_start[i] + g_bsum[i >> 8];
    g_start[i] = st;
    g_cur[i]   = st;
}

// ---------------- kernel: scatter edges into CSR-by-dst --------------------
__global__ void scatter_kernel(const int* __restrict__ src, const int* __restrict__ dst,
                               const float* __restrict__ ew) {
    int e = blockIdx.x * blockDim.x + threadIdx.x;
    if (e >= E_EDGES) return;
    int d   = dst[e];
    int pos = atomicAdd(&g_cur[d], 1);
    g_esrc[pos] = src[e];
    g_eww[pos]  = ew[e];
}

// ---------------- kernel: SGEMM with packed f32x2 FMA ----------------------
// g_proj = (feat * inv_out) @ g_w ; 128x128 block tile, BK=16, 256 threads,
// 8x8 register tile with accumulators packed as f32x2 pairs.
#define BM 128
#define BN 128
#define BK 16

__global__ __launch_bounds__(256, 1)
void gemm_kernel(const float* __restrict__ feat) {
    __shared__ __align__(16) float As[BK][BM];   // transposed A tile (scaled)
    __shared__ __align__(16) float Bs[BK][BN];

    const int tid = threadIdx.x;
    const int tx  = tid & 15;
    const int ty  = tid >> 4;
    const int block_row = blockIdx.x * BM;

    const int row_a = tid >> 1;
    const int ka    = (tid & 1) * 8;
    const int grow  = block_row + row_a;
    const bool row_ok = (grow < N_NODES);
    const float scale = row_ok ? g_inv_out[grow] : 0.0f;

    const int kb = tid >> 4;
    const int cb = (tid & 15) * 8;

    // packed accumulators: acc2[i][jp] = (acc[i][2jp], acc[i][2jp+1])
    unsigned long long acc2[8][4];
#pragma unroll
    for (int i = 0; i < 8; ++i)
#pragma unroll
        for (int j = 0; j < 4; ++j) acc2[i][j] = 0ull;   // bitwise (0.f, 0.f)

    for (int k0 = 0; k0 < IN_F; k0 += BK) {
        float4 a0 = make_float4(0.f,0.f,0.f,0.f);
        float4 a1 = a0;
        if (row_ok) {
            const float4* fp = reinterpret_cast<const float4*>(
                feat + (size_t)grow * IN_F + k0 + ka);
            a0 = fp[0];
            a1 = fp[1];
        }
        As[ka + 0][row_a] = a0.x * scale;
        As[ka + 1][row_a] = a0.y * scale;
        As[ka + 2][row_a] = a0.z * scale;
        As[ka + 3][row_a] = a0.w * scale;
        As[ka + 4][row_a] = a1.x * scale;
        As[ka + 5][row_a] = a1.y * scale;
        As[ka + 6][row_a] = a1.z * scale;
        As[ka + 7][row_a] = a1.w * scale;

        const float4* wp = reinterpret_cast<const float4*>(
            g_w + (size_t)(k0 + kb) * OUT_F + cb);
        float4 b0 = wp[0];
        float4 b1 = wp[1];
        *reinterpret_cast<float4*>(&Bs[kb][cb])     = b0;
        *reinterpret_cast<float4*>(&Bs[kb][cb + 4]) = b1;

        __syncthreads();

#pragma unroll
        for (int k = 0; k < BK; ++k) {
            float4 ar0 = *reinterpret_cast<const float4*>(&As[k][ty * 8]);
            float4 ar1 = *reinterpret_cast<const float4*>(&As[k][ty * 8 + 4]);
            const unsigned long long* brow =
                reinterpret_cast<const unsigned long long*>(&Bs[k][tx * 8]);
            unsigned long long b2_0 = brow[0];
            unsigned long long b2_1 = brow[1];
            unsigned long long b2_2 = brow[2];
            unsigned long long b2_3 = brow[3];
            float ar[8] = {ar0.x, ar0.y, ar0.z, ar0.w, ar1.x, ar1.y, ar1.z, ar1.w};
#pragma unroll
            for (int i = 0; i < 8; ++i) {
                unsigned long long a2;
                asm("mov.b64 %0, {%1, %1};" : "=l"(a2) : "f"(ar[i]));
                asm("fma.rn.f32x2 %0, %1, %2, %0;" : "+l"(acc2[i][0]) : "l"(a2), "l"(b2_0));
                asm("fma.rn.f32x2 %0, %1, %2, %0;" : "+l"(acc2[i][1]) : "l"(a2), "l"(b2_1));
                asm("fma.rn.f32x2 %0, %1, %2, %0;" : "+l"(acc2[i][2]) : "l"(a2), "l"(b2_2));
                asm("fma.rn.f32x2 %0, %1, %2, %0;" : "+l"(acc2[i][3]) : "l"(a2), "l"(b2_3));
            }
        }
        __syncthreads();
    }

#pragma unroll
    for (int i = 0; i < 8; ++i) {
        int r = block_row + ty * 8 + i;
        if (r >= N_NODES) continue;
        float o[8];
#pragma unroll
        for (int jp = 0; jp < 4; ++jp) {
            asm("mov.b64 {%0, %1}, %2;"
                : "=f"(o[2*jp]), "=f"(o[2*jp+1]) : "l"(acc2[i][jp]));
        }
        float* op = g_proj + (size_t)r * OUT_F + tx * 8;
        *reinterpret_cast<float4*>(op)     = make_float4(o[0], o[1], o[2], o[3]);
        *reinterpret_cast<float4*>(op + 4) = make_float4(o[4], o[5], o[6], o[7]);
    }
}

// ---------------- kernel: CSR gather + in-deg norm + bias (fused) ----------
// One warp per dst node. Lane handles one float4 of the 128-wide row.
__global__ __launch_bounds__(256)
void gather_kernel(float* __restrict__ out, const float* __restrict__ bias) {
    int warp = (blockIdx.x * blockDim.x + threadIdx.x) >> 5;
    int lane = threadIdx.x & 31;
    if (warp >= N_NODES) return;

    const int start = g_start[warp];
    const int deg   = (int)g_indeg[warp];

    float4 acc = make_float4(0.f, 0.f, 0.f, 0.f);

    for (int j = 0; j < deg; j += 32) {
        int idx = j + lane;
        int s = 0; float w = 0.f;
        if (idx < deg) {
            s = g_esrc[start + idx];
            w = g_eww[start + idx];
        }
        int m = min(32, deg - j);
        int t = 0;
        // 4-way unrolled: 4 independent gathers in flight
        for (; t + 4 <= m; t += 4) {
            int   s0 = __shfl_sync(0xffffffffu, s, t);
            int   s1 = __shfl_sync(0xffffffffu, s, t + 1);
            int   s2 = __shfl_sync(0xffffffffu, s, t + 2);
            int   s3 = __shfl_sync(0xffffffffu, s, t + 3);
            float w0 = __shfl_sync(0xffffffffu, w, t);
            float w1 = __shfl_sync(0xffffffffu, w, t + 1);
            float w2 = __shfl_sync(0xffffffffu, w, t + 2);
            float w3 = __shfl_sync(0xffffffffu, w, t + 3);
            float4 v0 = *reinterpret_cast<const float4*>(g_proj + (size_t)s0 * OUT_F + lane * 4);
            float4 v1 = *reinterpret_cast<const float4*>(g_proj + (size_t)s1 * OUT_F + lane * 4);
            float4 v2 = *reinterpret_cast<const float4*>(g_proj + (size_t)s2 * OUT_F + lane * 4);
            float4 v3 = *reinterpret_cast<const float4*>(g_proj + (size_t)s3 * OUT_F + lane * 4);
            acc.x = fmaf(v0.x, w0, acc.x); acc.y = fmaf(v0.y, w0, acc.y);
            acc.z = fmaf(v0.z, w0, acc.z); acc.w = fmaf(v0.w, w0, acc.w);
            acc.x = fmaf(v1.x, w1, acc.x); acc.y = fmaf(v1.y, w1, acc.y);
            acc.z = fmaf(v1.z, w1, acc.z); acc.w = fmaf(v1.w, w1, acc.w);
            acc.x = fmaf(v2.x, w2, acc.x); acc.y = fmaf(v2.y, w2, acc.y);
            acc.z = fmaf(v2.z, w2, acc.z); acc.w = fmaf(v2.w, w2, acc.w);
            acc.x = fmaf(v3.x, w3, acc.x); acc.y = fmaf(v3.y, w3, acc.y);
            acc.z = fmaf(v3.z, w3, acc.z); acc.w = fmaf(v3.w, w3, acc.w);
        }
        for (; t < m; ++t) {
            int   ss = __shfl_sync(0xffffffffu, s, t);
            float ww = __shfl_sync(0xffffffffu, w, t);
            float4 v = *reinterpret_cast<const float4*>(g_proj + (size_t)ss * OUT_F + lane * 4);
            acc.x = fmaf(v.x, ww, acc.x); acc.y = fmaf(v.y, ww, acc.y);
            acc.z = fmaf(v.z, ww, acc.z); acc.w = fmaf(v.w, ww, acc.w);
        }
    }

    const float si = g_inv_in[warp];
    float4 b = reinterpret_cast<const float4*>(bias)[lane];
    float4 o;
    o.x = fmaf(acc.x, si, b.x);
    o.y = fmaf(acc.y, si, b.y);
    o.z = fmaf(acc.z, si, b.z);
    o.w = fmaf(acc.w, si, b.w);
    *reinterpret_cast<float4*>(out + (size_t)warp * OUT_F + lane * 4) = o;
}

// ---------------- launch ----------------------------------------------------
extern "C" void kernel_launch(void* const* d_in, const int* in_sizes, int n_in,
                              void* d_out, int out_size) {
    const float* feat      = (const float*)d_in[0];
    const int*   src       = (const int*)  d_in[1];
    const int*   dst       = (const int*)  d_in[2];
    const float* ew        = (const float*)d_in[3];
    const float* weight    = (const float*)d_in[4];
    const float* bias      = (const float*)d_in[5];
    const float* mask_real = (const float*)d_in[6];
    float* out = (float*)d_out;

    const int nscan = (N_NODES + 255) / 256;   // 391

    zerodeg_kernel<<<nscan, 256>>>();
    count_kernel<<<(E_EDGES + 255) / 256, 256>>>(src, dst);
    maskw_kernel<<<(IN_F * OUT_F + 255) / 256, 256>>>(weight, mask_real);
    invdeg_kernel<<<nscan, 256>>>();
    scanA_kernel<<<nscan, 256>>>();
    scanB_kernel<<<1, 512>>>(nscan);
    scanC_kernel<<<nscan, 256>>>();
    scatter_kernel<<<(E_EDGES + 255) / 256, 256>>>(src, dst, ew);
    gemm_kernel<<<(N_NODES + BM - 1) / BM, 256>>>(feat);
    gather_kernel<<<(N_NODES * 32 + 255) / 256, 256>>>(out, bias);
}

// round 7
// speedup vs baseline: 2.0823x; 1.5715x over previous
#include <cuda_runtime.h>
#include <cstdint>

#define N_NODES 100000
#define E_EDGES 1600000
#define IN_F    256
#define OUT_F   128

// ---------------- device scratch (no runtime allocation allowed) ----------
__device__ float        g_proj[(size_t)N_NODES * OUT_F];   // projected feats [N, OUT]
__device__ float        g_w[IN_F * OUT_F];                  // masked weight [k][n], tf32-rounded
__device__ float        g_inv_out[N_NODES];
__device__ float        g_inv_in[N_NODES];
__device__ unsigned int g_outdeg[N_NODES];
__device__ unsigned int g_indeg[N_NODES];
// CSR-by-dst scratch
__device__ int          g_start[N_NODES];
__device__ int          g_cur[N_NODES];
__device__ int          g_bsum[512];
__device__ int          g_esrc[E_EDGES];
__device__ float        g_eww[E_EDGES];

__device__ __forceinline__ uint32_t f2tf32(float f) {
    uint32_t o;
    asm("cvt.rna.tf32.f32 %0, %1;" : "=r"(o) : "f"(f));
    return o;
}

// ---------------- kernel 1: zero degree counters ---------------------------
__global__ void zerodeg_kernel() {
    int i = blockIdx.x * blockDim.x + threadIdx.x;
    if (i < N_NODES) { g_outdeg[i] = 0u; g_indeg[i] = 0u; }
}

// ---------------- kernel 2: count degrees ---------------------------------
__global__ void count_kernel(const int* __restrict__ src, const int* __restrict__ dst) {
    int e = blockIdx.x * blockDim.x + threadIdx.x;
    if (e >= E_EDGES) return;
    atomicAdd(&g_outdeg[src[e]], 1u);
    atomicAdd(&g_indeg[dst[e]], 1u);
}

// ---------------- kernel 3: masked weight (tf32-rounded) -------------------
__global__ void maskw_kernel(const float* __restrict__ weight,
                             const float* __restrict__ mask_real) {
    int i = blockIdx.x * blockDim.x + threadIdx.x;
    if (i >= IN_F * OUT_F) return;
    float v = (mask_real[i] > 0.5f) ? weight[i] : 0.0f;
    g_w[i] = __uint_as_float(f2tf32(v));
}

// ---------------- kernel 4: inverse sqrt degrees ---------------------------
__global__ void invdeg_kernel() {
    int i = blockIdx.x * blockDim.x + threadIdx.x;
    if (i >= N_NODES) return;
    g_inv_out[i] = rsqrtf(fmaxf((float)g_outdeg[i], 1.0f));
    g_inv_in[i]  = rsqrtf(fmaxf((float)g_indeg[i], 1.0f));
}

// ---------------- scan kernels ---------------------------------------------
__global__ void scanA_kernel() {
    __shared__ int s[256];
    int t = threadIdx.x;
    int i = blockIdx.x * 256 + t;
    int v = (i < N_NODES) ? (int)g_indeg[i] : 0;
    s[t] = v;
    __syncthreads();
#pragma unroll
    for (int off = 1; off < 256; off <<= 1) {
        int add = (t >= off) ? s[t - off] : 0;
        __syncthreads();
        s[t] += add;
        __syncthreads();
    }
    if (i < N_NODES) g_start[i] = s[t] - v;
    if (t == 255) g_bsum[blockIdx.x] = s[255];
}

__global__ void scanB_kernel(int nblocks) {
    __shared__ int s[512];
    int t = threadIdx.x;
    int v = (t < nblocks) ? g_bsum[t] : 0;
    s[t] = v;
    __syncthreads();
#pragma unroll
    for (int off = 1; off < 512; off <<= 1) {
        int add = (t >= off) ? s[t - off] : 0;
        __syncthreads();
        s[t] += add;
        __syncthreads();
    }
    if (t < nblocks) g_bsum[t] = s[t] - v;
}

__global__ void scanC_kernel() {
    int i = blockIdx.x * blockDim.x + threadIdx.x;
    if (i >= N_NODES) return;
    int st = g_start[i] + g_bsum[i >> 8];
    g_start[i] = st;
    g_cur[i]   = st;
}

// ---------------- kernel: scatter edges into CSR-by-dst --------------------
__global__ void scatter_kernel(const int* __restrict__ src, const int* __restrict__ dst,
                               const float* __restrict__ ew) {
    int e = blockIdx.x * blockDim.x + threadIdx.x;
    if (e >= E_EDGES) return;
    int d   = dst[e];
    int pos = atomicAdd(&g_cur[d], 1);
    g_esrc[pos] = src[e];
    g_eww[pos]  = ew[e];
}

// ================= tf32 mma.sync GEMM: g_proj = (feat * inv_out) @ W =======
// CTA tile 128x128, BK=32, 256 threads = 8 warps (2 x 4), warp tile 64x32.
// A smem [128][36] (pad->conflict-free frag loads), B smem [32][136].
#define ASTRIDE 36
#define BSTRIDE 136

__global__ void __launch_bounds__(256, 2)
gemm_mma_kernel(const float* __restrict__ feat) {
    __shared__ __align__(16) float As[128 * ASTRIDE];   // [m][k]
    __shared__ __align__(16) float Bs[32 * BSTRIDE];    // [k][n]

    const int tid  = threadIdx.x;
    const int wid  = tid >> 5;
    const int lane = tid & 31;
    const int g    = lane >> 2;    // group id 0..7
    const int t4   = lane & 3;     // thread-in-group 0..3
    const int wm   = wid >> 2;     // 0..1 -> 64-row band
    const int wn   = wid & 3;      // 0..3 -> 32-col band
    const int block_row = blockIdx.x * 128;

    // accumulators: [mi][ni][4]
    float acc[4][4][4];
#pragma unroll
    for (int mi = 0; mi < 4; ++mi)
#pragma unroll
        for (int ni = 0; ni < 4; ++ni)
#pragma unroll
            for (int r = 0; r < 4; ++r) acc[mi][ni][r] = 0.0f;

    // global->smem mapping: 1024 float4 per tile, 4 per thread
    // A: float4 f -> row f/8, colgroup f%8
    // B: float4 f -> k f/32, ngroup f%32
    const uint32_t* As_u = reinterpret_cast<const uint32_t*>(As);
    const uint32_t* Bs_u = reinterpret_cast<const uint32_t*>(Bs);

    for (int k0 = 0; k0 < IN_F; k0 += 32) {
#pragma unroll
        for (int i = 0; i < 4; ++i) {
            int f   = tid + i * 256;
            int row = f >> 3;
            int c4  = (f & 7) * 4;
            int grow = block_row + row;
            float4 v = make_float4(0.f, 0.f, 0.f, 0.f);
            float  sc = 0.f;
            if (grow < N_NODES) {
                sc = g_inv_out[grow];
                v = *reinterpret_cast<const float4*>(feat + (size_t)grow * IN_F + k0 + c4);
            }
            float4 o;
            o.x = __uint_as_float(f2tf32(v.x * sc));
            o.y = __uint_as_float(f2tf32(v.y * sc));
            o.z = __uint_as_float(f2tf32(v.z * sc));
            o.w = __uint_as_float(f2tf32(v.w * sc));
            *reinterpret_cast<float4*>(&As[row * ASTRIDE + c4]) = o;
        }
#pragma unroll
        for (int i = 0; i < 4; ++i) {
            int f  = tid + i * 256;
            int kk = f >> 5;
            int n4 = (f & 31) * 4;
            float4 v = *reinterpret_cast<const float4*>(g_w + (size_t)(k0 + kk) * OUT_F + n4);
            *reinterpret_cast<float4*>(&Bs[kk * BSTRIDE + n4]) = v;  // already tf32-rounded
        }
        __syncthreads();

#pragma unroll
        for (int ks = 0; ks < 4; ++ks) {
            const int kb = ks * 8;
            uint32_t a[4][4], b[4][2];
#pragma unroll
            for (int mi = 0; mi < 4; ++mi) {
                int r = wm * 64 + mi * 16 + g;
                a[mi][0] = As_u[(r)     * ASTRIDE + kb + t4];
                a[mi][1] = As_u[(r + 8) * ASTRIDE + kb + t4];
                a[mi][2] = As_u[(r)     * ASTRIDE + kb + t4 + 4];
                a[mi][3] = As_u[(r + 8) * ASTRIDE + kb + t4 + 4];
            }
#pragma unroll
            for (int ni = 0; ni < 4; ++ni) {
                int cn = wn * 32 + ni * 8 + g;
                b[ni][0] = Bs_u[(kb + t4)     * BSTRIDE + cn];
                b[ni][1] = Bs_u[(kb + t4 + 4) * BSTRIDE + cn];
            }
#pragma unroll
            for (int mi = 0; mi < 4; ++mi)
#pragma unroll
                for (int ni = 0; ni < 4; ++ni) {
                    asm volatile(
                        "mma.sync.aligned.m16n8k8.row.col.f32.tf32.tf32.f32 "
                        "{%0,%1,%2,%3}, {%4,%5,%6,%7}, {%8,%9}, {%0,%1,%2,%3};"
                        : "+f"(acc[mi][ni][0]), "+f"(acc[mi][ni][1]),
                          "+f"(acc[mi][ni][2]), "+f"(acc[mi][ni][3])
                        : "r"(a[mi][0]), "r"(a[mi][1]), "r"(a[mi][2]), "r"(a[mi][3]),
                          "r"(b[ni][0]), "r"(b[ni][1]));
                }
        }
        __syncthreads();
    }

    // epilogue: c0,c1 at (row=base+g, col=2*t4+{0,1}); c2,c3 at row+8
#pragma unroll
    for (int mi = 0; mi < 4; ++mi) {
        int r0 = block_row + wm * 64 + mi * 16 + g;
        int r1 = r0 + 8;
#pragma unroll
        for (int ni = 0; ni < 4; ++ni) {
            int col = wn * 32 + ni * 8 + 2 * t4;
            if (r0 < N_NODES) {
                float2 v = make_float2(acc[mi][ni][0], acc[mi][ni][1]);
                *reinterpret_cast<float2*>(g_proj + (size_t)r0 * OUT_F + col) = v;
            }
            if (r1 < N_NODES) {
                float2 v = make_float2(acc[mi][ni][2], acc[mi][ni][3]);
                *reinterpret_cast<float2*>(g_proj + (size_t)r1 * OUT_F + col) = v;
            }
        }
    }
}

// ---------------- kernel: CSR gather + in-deg norm + bias (fused) ----------
__global__ __launch_bounds__(256)
void gather_kernel(float* __restrict__ out, const float* __restrict__ bias) {
    int warp = (blockIdx.x * blockDim.x + threadIdx.x) >> 5;
    int lane = threadIdx.x & 31;
    if (warp >= N_NODES) return;

    const int start = g_start[warp];
    const int deg   = (int)g_indeg[warp];

    float4 acc = make_float4(0.f, 0.f, 0.f, 0.f);

    for (int j = 0; j < deg; j += 32) {
        int idx = j + lane;
        int s = 0; float w = 0.f;
        if (idx < deg) {
            s = g_esrc[start + idx];
            w = g_eww[start + idx];
        }
        int m = min(32, deg - j);
        int t = 0;
        for (; t + 4 <= m; t += 4) {
            int   s0 = __shfl_sync(0xffffffffu, s, t);
            int   s1 = __shfl_sync(0xffffffffu, s, t + 1);
            int   s2 = __shfl_sync(0xffffffffu, s, t + 2);
            int   s3 = __shfl_sync(0xffffffffu, s, t + 3);
            float w0 = __shfl_sync(0xffffffffu, w, t);
            float w1 = __shfl_sync(0xffffffffu, w, t + 1);
            float w2 = __shfl_sync(0xffffffffu, w, t + 2);
            float w3 = __shfl_sync(0xffffffffu, w, t + 3);
            float4 v0 = *reinterpret_cast<const float4*>(g_proj + (size_t)s0 * OUT_F + lane * 4);
            float4 v1 = *reinterpret_cast<const float4*>(g_proj + (size_t)s1 * OUT_F + lane * 4);
            float4 v2 = *reinterpret_cast<const float4*>(g_proj + (size_t)s2 * OUT_F + lane * 4);
            float4 v3 = *reinterpret_cast<const float4*>(g_proj + (size_t)s3 * OUT_F + lane * 4);
            acc.x = fmaf(v0.x, w0, acc.x); acc.y = fmaf(v0.y, w0, acc.y);
            acc.z = fmaf(v0.z, w0, acc.z); acc.w = fmaf(v0.w, w0, acc.w);
            acc.x = fmaf(v1.x, w1, acc.x); acc.y = fmaf(v1.y, w1, acc.y);
            acc.z = fmaf(v1.z, w1, acc.z); acc.w = fmaf(v1.w, w1, acc.w);
            acc.x = fmaf(v2.x, w2, acc.x); acc.y = fmaf(v2.y, w2, acc.y);
            acc.z = fmaf(v2.z, w2, acc.z); acc.w = fmaf(v2.w, w2, acc.w);
            acc.x = fmaf(v3.x, w3, acc.x); acc.y = fmaf(v3.y, w3, acc.y);
            acc.z = fmaf(v3.z, w3, acc.z); acc.w = fmaf(v3.w, w3, acc.w);
        }
        for (; t < m; ++t) {
            int   ss = __shfl_sync(0xffffffffu, s, t);
            float ww = __shfl_sync(0xffffffffu, w, t);
            float4 v = *reinterpret_cast<const float4*>(g_proj + (size_t)ss * OUT_F + lane * 4);
            acc.x = fmaf(v.x, ww, acc.x); acc.y = fmaf(v.y, ww, acc.y);
            acc.z = fmaf(v.z, ww, acc.z); acc.w = fmaf(v.w, ww, acc.w);
        }
    }

    const float si = g_inv_in[warp];
    float4 b = reinterpret_cast<const float4*>(bias)[lane];
    float4 o;
    o.x = fmaf(acc.x, si, b.x);
    o.y = fmaf(acc.y, si, b.y);
    o.z = fmaf(acc.z, si, b.z);
    o.w = fmaf(acc.w, si, b.w);
    *reinterpret_cast<float4*>(out + (size_t)warp * OUT_F + lane * 4) = o;
}

// ---------------- launch ----------------------------------------------------
extern "C" void kernel_launch(void* const* d_in, const int* in_sizes, int n_in,
                              void* d_out, int out_size) {
    const float* feat      = (const float*)d_in[0];
    const int*   src       = (const int*)  d_in[1];
    const int*   dst       = (const int*)  d_in[2];
    const float* ew        = (const float*)d_in[3];
    const float* weight    = (const float*)d_in[4];
    const float* bias      = (const float*)d_in[5];
    const float* mask_real = (const float*)d_in[6];
    float* out = (float*)d_out;

    const int nscan = (N_NODES + 255) / 256;   // 391

    zerodeg_kernel<<<nscan, 256>>>();
    count_kernel<<<(E_EDGES + 255) / 256, 256>>>(src, dst);
    maskw_kernel<<<(IN_F * OUT_F + 255) / 256, 256>>>(weight, mask_real);
    invdeg_kernel<<<nscan, 256>>>();
    scanA_kernel<<<nscan, 256>>>();
    scanB_kernel<<<1, 512>>>(nscan);
    scanC_kernel<<<nscan, 256>>>();
    scatter_kernel<<<(E_EDGES + 255) / 256, 256>>>(src, dst, ew);
    gemm_mma_kernel<<<(N_NODES + 127) / 128, 256>>>(feat);
    gather_kernel<<<(N_NODES * 32 + 255) / 256, 256>>>(out, bias);
}

// round 8
// speedup vs baseline: 2.6082x; 1.2526x over previous
#include <cuda_runtime.h>
#include <cuda_fp16.h>
#include <cstdint>

#define N_NODES 100000
#define E_EDGES 1600000
#define IN_F    256
#define OUT_F   128

// ---------------- device scratch (no runtime allocation allowed) ----------
__device__ __half       g_proj[(size_t)N_NODES * OUT_F];   // projected feats [N, OUT], fp16
__device__ float        g_w[IN_F * OUT_F];                  // masked weight [k][n], tf32-rounded
__device__ float        g_inv_out[N_NODES];
__device__ float        g_inv_in[N_NODES];
__device__ unsigned int g_outdeg[N_NODES];
__device__ unsigned int g_indeg[N_NODES];
// CSR-by-dst scratch
__device__ int          g_start[N_NODES];
__device__ int          g_cur[N_NODES];
__device__ int          g_bsum[512];
__device__ int2         g_edge[E_EDGES];     // (src, weight-bits) per CSR slot

__device__ __forceinline__ uint32_t f2tf32(float f) {
    uint32_t o;
    asm("cvt.rna.tf32.f32 %0, %1;" : "=r"(o) : "f"(f));
    return o;
}

// ---------------- fused: zero degree counters + masked weight --------------
__global__ void prep_kernel(const float* __restrict__ weight,
                            const float* __restrict__ mask_real) {
    int i = blockIdx.x * blockDim.x + threadIdx.x;
    if (i < N_NODES) { g_outdeg[i] = 0u; g_indeg[i] = 0u; }
    if (i < IN_F * OUT_F) {
        float v = (mask_real[i] > 0.5f) ? weight[i] : 0.0f;
        g_w[i] = __uint_as_float(f2tf32(v));
    }
}

// ---------------- count degrees --------------------------------------------
__global__ void count_kernel(const int* __restrict__ src, const int* __restrict__ dst) {
    int e = blockIdx.x * blockDim.x + threadIdx.x;
    if (e >= E_EDGES) return;
    atomicAdd(&g_outdeg[src[e]], 1u);
    atomicAdd(&g_indeg[dst[e]], 1u);
}

// ---------------- scanA fused with inv-degree computation ------------------
__global__ void scanA_kernel() {
    __shared__ int s[256];
    int t = threadIdx.x;
    int i = blockIdx.x * 256 + t;
    int v = 0;
    if (i < N_NODES) {
        unsigned int id = g_indeg[i];
        v = (int)id;
        g_inv_in[i]  = rsqrtf(fmaxf((float)id, 1.0f));
        g_inv_out[i] = rsqrtf(fmaxf((float)g_outdeg[i], 1.0f));
    }
    s[t] = v;
    __syncthreads();
#pragma unroll
    for (int off = 1; off < 256; off <<= 1) {
        int add = (t >= off) ? s[t - off] : 0;
        __syncthreads();
        s[t] += add;
        __syncthreads();
    }
    if (i < N_NODES) g_start[i] = s[t] - v;
    if (t == 255) g_bsum[blockIdx.x] = s[255];
}

__global__ void scanB_kernel(int nblocks) {
    __shared__ int s[512];
    int t = threadIdx.x;
    int v = (t < nblocks) ? g_bsum[t] : 0;
    s[t] = v;
    __syncthreads();
#pragma unroll
    for (int off = 1; off < 512; off <<= 1) {
        int add = (t >= off) ? s[t - off] : 0;
        __syncthreads();
        s[t] += add;
        __syncthreads();
    }
    if (t < nblocks) g_bsum[t] = s[t] - v;
}

__global__ void scanC_kernel() {
    int i = blockIdx.x * blockDim.x + threadIdx.x;
    if (i >= N_NODES) return;
    int st = g_start[i] + g_bsum[i >> 8];
    g_start[i] = st;
    g_cur[i]   = st;
}

// ---------------- scatter edges into CSR-by-dst (packed int2) --------------
__global__ void scatter_kernel(const int* __restrict__ src, const int* __restrict__ dst,
                               const float* __restrict__ ew) {
    int e = blockIdx.x * blockDim.x + threadIdx.x;
    if (e >= E_EDGES) return;
    int d   = dst[e];
    int pos = atomicAdd(&g_cur[d], 1);
    g_edge[pos] = make_int2(src[e], __float_as_int(ew[e]));
}

// ================= tf32 mma.sync GEMM: g_proj = (feat * inv_out) @ W =======
// CTA tile 128x128, BK=32, 256 threads = 8 warps (2 x 4), warp tile 64x32.
#define ASTRIDE 36
#define BSTRIDE 136

__global__ void __launch_bounds__(256, 2)
gemm_mma_kernel(const float* __restrict__ feat) {
    __shared__ __align__(16) float As[128 * ASTRIDE];   // [m][k]
    __shared__ __align__(16) float Bs[32 * BSTRIDE];    // [k][n]

    const int tid  = threadIdx.x;
    const int wid  = tid >> 5;
    const int lane = tid & 31;
    const int g    = lane >> 2;
    const int t4   = lane & 3;
    const int wm   = wid >> 2;
    const int wn   = wid & 3;
    const int block_row = blockIdx.x * 128;

    float acc[4][4][4];
#pragma unroll
    for (int mi = 0; mi < 4; ++mi)
#pragma unroll
        for (int ni = 0; ni < 4; ++ni)
#pragma unroll
            for (int r = 0; r < 4; ++r) acc[mi][ni][r] = 0.0f;

    const uint32_t* As_u = reinterpret_cast<const uint32_t*>(As);
    const uint32_t* Bs_u = reinterpret_cast<const uint32_t*>(Bs);

    for (int k0 = 0; k0 < IN_F; k0 += 32) {
#pragma unroll
        for (int i = 0; i < 4; ++i) {
            int f   = tid + i * 256;
            int row = f >> 3;
            int c4  = (f & 7) * 4;
            int grow = block_row + row;
            float4 v = make_float4(0.f, 0.f, 0.f, 0.f);
            float  sc = 0.f;
            if (grow < N_NODES) {
                sc = g_inv_out[grow];
                v = *reinterpret_cast<const float4*>(feat + (size_t)grow * IN_F + k0 + c4);
            }
            float4 o;
            o.x = __uint_as_float(f2tf32(v.x * sc));
            o.y = __uint_as_float(f2tf32(v.y * sc));
            o.z = __uint_as_float(f2tf32(v.z * sc));
            o.w = __uint_as_float(f2tf32(v.w * sc));
            *reinterpret_cast<float4*>(&As[row * ASTRIDE + c4]) = o;
        }
#pragma unroll
        for (int i = 0; i < 4; ++i) {
            int f  = tid + i * 256;
            int kk = f >> 5;
            int n4 = (f & 31) * 4;
            float4 v = *reinterpret_cast<const float4*>(g_w + (size_t)(k0 + kk) * OUT_F + n4);
            *reinterpret_cast<float4*>(&Bs[kk * BSTRIDE + n4]) = v;
        }
        __syncthreads();

#pragma unroll
        for (int ks = 0; ks < 4; ++ks) {
            const int kb = ks * 8;
            uint32_t a[4][4], b[4][2];
#pragma unroll
            for (int mi = 0; mi < 4; ++mi) {
                int r = wm * 64 + mi * 16 + g;
                a[mi][0] = As_u[(r)     * ASTRIDE + kb + t4];
                a[mi][1] = As_u[(r + 8) * ASTRIDE + kb + t4];
                a[mi][2] = As_u[(r)     * ASTRIDE + kb + t4 + 4];
                a[mi][3] = As_u[(r + 8) * ASTRIDE + kb + t4 + 4];
            }
#pragma unroll
            for (int ni = 0; ni < 4; ++ni) {
                int cn = wn * 32 + ni * 8 + g;
                b[ni][0] = Bs_u[(kb + t4)     * BSTRIDE + cn];
                b[ni][1] = Bs_u[(kb + t4 + 4) * BSTRIDE + cn];
            }
#pragma unroll
            for (int mi = 0; mi < 4; ++mi)
#pragma unroll
                for (int ni = 0; ni < 4; ++ni) {
                    asm volatile(
                        "mma.sync.aligned.m16n8k8.row.col.f32.tf32.tf32.f32 "
                        "{%0,%1,%2,%3}, {%4,%5,%6,%7}, {%8,%9}, {%0,%1,%2,%3};"
                        : "+f"(acc[mi][ni][0]), "+f"(acc[mi][ni][1]),
                          "+f"(acc[mi][ni][2]), "+f"(acc[mi][ni][3])
                        : "r"(a[mi][0]), "r"(a[mi][1]), "r"(a[mi][2]), "r"(a[mi][3]),
                          "r"(b[ni][0]), "r"(b[ni][1]));
                }
        }
        __syncthreads();
    }

    // epilogue: adjacent column pairs -> half2 stores
#pragma unroll
    for (int mi = 0; mi < 4; ++mi) {
        int r0 = block_row + wm * 64 + mi * 16 + g;
        int r1 = r0 + 8;
#pragma unroll
        for (int ni = 0; ni < 4; ++ni) {
            int col = wn * 32 + ni * 8 + 2 * t4;
            if (r0 < N_NODES) {
                __half2 h = __floats2half2_rn(acc[mi][ni][0], acc[mi][ni][1]);
                *reinterpret_cast<__half2*>(g_proj + (size_t)r0 * OUT_F + col) = h;
            }
            if (r1 < N_NODES) {
                __half2 h = __floats2half2_rn(acc[mi][ni][2], acc[mi][ni][3]);
                *reinterpret_cast<__half2*>(g_proj + (size_t)r1 * OUT_F + col) = h;
            }
        }
    }
}

// ---------------- CSR gather (fp16 rows) + in-deg norm + bias --------------
// One warp per dst node. Lane handles 4 halfs (8B) of the 128-wide row.
__global__ __launch_bounds__(256)
void gather_kernel(float* __restrict__ out, const float* __restrict__ bias) {
    int warp = (blockIdx.x * blockDim.x + threadIdx.x) >> 5;
    int lane = threadIdx.x & 31;
    if (warp >= N_NODES) return;

    const int start = g_start[warp];
    const int deg   = (int)g_indeg[warp];

    float4 acc = make_float4(0.f, 0.f, 0.f, 0.f);

    for (int j = 0; j < deg; j += 32) {
        int idx = j + lane;
        int s = 0; float w = 0.f;
        if (idx < deg) {
            int2 e = g_edge[start + idx];
            s = e.x;
            w = __int_as_float(e.y);
        }
        int m = min(32, deg - j);
        int t = 0;
        for (; t + 4 <= m; t += 4) {
            int   s0 = __shfl_sync(0xffffffffu, s, t);
            int   s1 = __shfl_sync(0xffffffffu, s, t + 1);
            int   s2 = __shfl_sync(0xffffffffu, s, t + 2);
            int   s3 = __shfl_sync(0xffffffffu, s, t + 3);
            float w0 = __shfl_sync(0xffffffffu, w, t);
            float w1 = __shfl_sync(0xffffffffu, w, t + 1);
            float w2 = __shfl_sync(0xffffffffu, w, t + 2);
            float w3 = __shfl_sync(0xffffffffu, w, t + 3);
            uint2 u0 = *reinterpret_cast<const uint2*>(g_proj + (size_t)s0 * OUT_F + lane * 4);
            uint2 u1 = *reinterpret_cast<const uint2*>(g_proj + (size_t)s1 * OUT_F + lane * 4);
            uint2 u2 = *reinterpret_cast<const uint2*>(g_proj + (size_t)s2 * OUT_F + lane * 4);
            uint2 u3 = *reinterpret_cast<const uint2*>(g_proj + (size_t)s3 * OUT_F + lane * 4);
            float2 a0 = __half22float2(*reinterpret_cast<__half2*>(&u0.x));
            float2 b0 = __half22float2(*reinterpret_cast<__half2*>(&u0.y));
            float2 a1 = __half22float2(*reinterpret_cast<__half2*>(&u1.x));
            float2 b1 = __half22float2(*reinterpret_cast<__half2*>(&u1.y));
            float2 a2 = __half22float2(*reinterpret_cast<__half2*>(&u2.x));
            float2 b2 = __half22float2(*reinterpret_cast<__half2*>(&u2.y));
            float2 a3 = __half22float2(*reinterpret_cast<__half2*>(&u3.x));
            float2 b3 = __half22float2(*reinterpret_cast<__half2*>(&u3.y));
            acc.x = fmaf(a0.x, w0, acc.x); acc.y = fmaf(a0.y, w0, acc.y);
            acc.z = fmaf(b0.x, w0, acc.z); acc.w = fmaf(b0.y, w0, acc.w);
            acc.x = fmaf(a1.x, w1, acc.x); acc.y = fmaf(a1.y, w1, acc.y);
            acc.z = fmaf(b1.x, w1, acc.z); acc.w = fmaf(b1.y, w1, acc.w);
            acc.x = fmaf(a2.x, w2, acc.x); acc.y = fmaf(a2.y, w2, acc.y);
            acc.z = fmaf(b2.x, w2, acc.z); acc.w = fmaf(b2.y, w2, acc.w);
            acc.x = fmaf(a3.x, w3, acc.x); acc.y = fmaf(a3.y, w3, acc.y);
            acc.z = fmaf(b3.x, w3, acc.z); acc.w = fmaf(b3.y, w3, acc.w);
        }
        for (; t < m; ++t) {
            int   ss = __shfl_sync(0xffffffffu, s, t);
            float ww = __shfl_sync(0xffffffffu, w, t);
            uint2 u = *reinterpret_cast<const uint2*>(g_proj + (size_t)ss * OUT_F + lane * 4);
            float2 a = __half22float2(*reinterpret_cast<__half2*>(&u.x));
            float2 b = __half22float2(*reinterpret_cast<__half2*>(&u.y));
            acc.x = fmaf(a.x, ww, acc.x); acc.y = fmaf(a.y, ww, acc.y);
            acc.z = fmaf(b.x, ww, acc.z); acc.w = fmaf(b.y, ww, acc.w);
        }
    }

    const float si = g_inv_in[warp];
    float4 b = reinterpret_cast<const float4*>(bias)[lane];
    float4 o;
    o.x = fmaf(acc.x, si, b.x);
    o.y = fmaf(acc.y, si, b.y);
    o.z = fmaf(acc.z, si, b.z);
    o.w = fmaf(acc.w, si, b.w);
    *reinterpret_cast<float4*>(out + (size_t)warp * OUT_F + lane * 4) = o;
}

// ---------------- launch ----------------------------------------------------
extern "C" void kernel_launch(void* const* d_in, const int* in_sizes, int n_in,
                              void* d_out, int out_size) {
    const float* feat      = (const float*)d_in[0];
    const int*   src       = (const int*)  d_in[1];
    const int*   dst       = (const int*)  d_in[2];
    const float* ew        = (const float*)d_in[3];
    const float* weight    = (const float*)d_in[4];
    const float* bias      = (const float*)d_in[5];
    const float* mask_real = (const float*)d_in[6];
    float* out = (float*)d_out;

    const int nscan = (N_NODES + 255) / 256;   // 391

    prep_kernel<<<nscan, 256>>>(weight, mask_real);
    count_kernel<<<(E_EDGES + 255) / 256, 256>>>(src, dst);
    scanA_kernel<<<nscan, 256>>>();
    scanB_kernel<<<1, 512>>>(nscan);
    scanC_kernel<<<nscan, 256>>>();
    scatter_kernel<<<(E_EDGES + 255) / 256, 256>>>(src, dst, ew);
    gemm_mma_kernel<<<(N_NODES + 127) / 128, 256>>>(feat);
    gather_kernel<<<(N_NODES * 32 + 255) / 256, 256>>>(out, bias);
}

// round 10
// speedup vs baseline: 2.6838x; 1.0290x over previous
#include <cuda_runtime.h>
#include <cuda_fp16.h>
#include <cstdint>

#define N_NODES 100000
#define E_EDGES 1600000
#define IN_F    256
#define OUT_F   128

// ---------------- device scratch (no runtime allocation allowed) ----------
__device__ __half       g_proj[(size_t)N_NODES * OUT_F];   // projected feats [N, OUT], fp16 (UNSCALED)
__device__ float        g_w[IN_F * OUT_F];                  // masked weight [k][n], tf32-rounded
__device__ float        g_inv_out[N_NODES];
__device__ float        g_inv_in[N_NODES];
__device__ unsigned int g_outdeg[N_NODES];
__device__ unsigned int g_indeg[N_NODES];
// CSR-by-dst scratch
__device__ int          g_start[N_NODES];
__device__ int          g_cur[N_NODES];
__device__ int          g_bsum[512];
__device__ int2         g_edge[E_EDGES];     // (src, (ew*inv_out[src])-bits) per CSR slot

__device__ __forceinline__ uint32_t f2tf32(float f) {
    uint32_t o;
    asm("cvt.rna.tf32.f32 %0, %1;" : "=r"(o) : "f"(f));
    return o;
}
__device__ __forceinline__ uint32_t smem_u32(const void* p) {
    uint32_t a;
    asm("{ .reg .u64 t; cvta.to.shared.u64 t, %1; cvt.u32.u64 %0, t; }"
        : "=r"(a) : "l"(p));
    return a;
}
#define CP_ASYNC16(dst, src) \
    asm volatile("cp.async.cg.shared.global [%0], [%1], 16;" :: "r"(dst), "l"(src) : "memory")
#define CP_ASYNC16_Z(dst, src, sz) \
    asm volatile("cp.async.cg.shared.global [%0], [%1], 16, %2;" :: "r"(dst), "l"(src), "r"(sz) : "memory")
#define CP_COMMIT() asm volatile("cp.async.commit_group;" ::: "memory")
#define CP_WAIT1()  asm volatile("cp.async.wait_group 1;" ::: "memory")
#define CP_WAIT0()  asm volatile("cp.async.wait_group 0;" ::: "memory")

// ---------------- fused: zero degree counters + masked weight --------------
__global__ void prep_kernel(const float* __restrict__ weight,
                            const float* __restrict__ mask_real) {
    int i = blockIdx.x * blockDim.x + threadIdx.x;
    if (i < N_NODES) { g_outdeg[i] = 0u; g_indeg[i] = 0u; }
    if (i < IN_F * OUT_F) {
        float v = (mask_real[i] > 0.5f) ? weight[i] : 0.0f;
        g_w[i] = __uint_as_float(f2tf32(v));
    }
}

// ---------------- count degrees (2 edges/thread) ---------------------------
__global__ void count_kernel(const int2* __restrict__ src2, const int2* __restrict__ dst2) {
    int e = blockIdx.x * blockDim.x + threadIdx.x;
    if (e >= E_EDGES / 2) return;
    int2 s = src2[e];
    int2 d = dst2[e];
    atomicAdd(&g_outdeg[s.x], 1u);
    atomicAdd(&g_outdeg[s.y], 1u);
    atomicAdd(&g_indeg[d.x], 1u);
    atomicAdd(&g_indeg[d.y], 1u);
}

// ---------------- scanA: block-local prefix + inv degrees ------------------
__global__ void scanA_kernel() {
    __shared__ int s[256];
    int t = threadIdx.x;
    int i = blockIdx.x * 256 + t;
    int v = 0;
    if (i < N_NODES) {
        unsigned int id = g_indeg[i];
        v = (int)id;
        g_inv_in[i]  = rsqrtf(fmaxf((float)id, 1.0f));
        g_inv_out[i] = rsqrtf(fmaxf((float)g_outdeg[i], 1.0f));
    }
    s[t] = v;
    __syncthreads();
#pragma unroll
    for (int off = 1; off < 256; off <<= 1) {
        int add = (t >= off) ? s[t - off] : 0;
        __syncthreads();
        s[t] += add;
        __syncthreads();
    }
    if (i < N_NODES) g_start[i] = s[t] - v;
    if (t == 255) g_bsum[blockIdx.x] = s[255];
}

// ---------------- scanC: per-block prefix of bsum + finalize ----------------
__global__ void scanC_kernel() {
    __shared__ int wsum[8];
    __shared__ int soff;
    const int b = blockIdx.x;
    const int t = threadIdx.x;
    int part = 0;
    for (int j = t; j < b; j += 256) part += g_bsum[j];
#pragma unroll
    for (int o = 16; o; o >>= 1) part += __shfl_down_sync(0xffffffffu, part, o);
    if ((t & 31) == 0) wsum[t >> 5] = part;
    __syncthreads();
    if (t == 0) {
        int sum = 0;
#pragma unroll
        for (int w = 0; w < 8; ++w) sum += wsum[w];
        soff = sum;
    }
    __syncthreads();
    int i = b * 256 + t;
    if (i < N_NODES) {
        int st = g_start[i] + soff;
        g_start[i] = st;
        g_cur[i]   = st;
    }
}

// ---------------- scatter edges into CSR-by-dst (w *= inv_out[src]) --------
__global__ void scatter_kernel(const int* __restrict__ src, const int* __restrict__ dst,
                               const float* __restrict__ ew) {
    int e = blockIdx.x * blockDim.x + threadIdx.x;
    if (e >= E_EDGES) return;
    int s   = src[e];
    int d   = dst[e];
    float w = ew[e] * g_inv_out[s];
    int pos = atomicAdd(&g_cur[d], 1);
    g_edge[pos] = make_int2(s, __float_as_int(w));
}

// ================= tf32 mma.sync GEMM (cp.async 2-stage): proj = feat @ W ==
// CTA tile 128x128, BK=32, 256 threads = 8 warps (2 x 4), warp tile 64x32.
#define ASTRIDE 36
#define BSTRIDE 136
#define A_FLOATS (128 * ASTRIDE)      // 4608
#define B_FLOATS (32 * BSTRIDE)       // 4352
#define SMEM_FLOATS (2 * A_FLOATS + 2 * B_FLOATS)   // 17920 -> 71680 B

__global__ void __launch_bounds__(256, 2)
gemm_mma_kernel(const float* __restrict__ feat) {
    extern __shared__ __align__(16) float smem[];
    float* Asf = smem;                       // 2 stages of A
    float* Bsf = smem + 2 * A_FLOATS;        // 2 stages of B
    const uint32_t as_base = smem_u32(Asf);
    const uint32_t bs_base = smem_u32(Bsf);

    const int tid  = threadIdx.x;
    const int wid  = tid >> 5;
    const int lane = tid & 31;
    const int g    = lane >> 2;
    const int t4   = lane & 3;
    const int wm   = wid >> 2;
    const int wn   = wid & 3;
    const int block_row = blockIdx.x * 128;

    float acc[4][4][4];
#pragma unroll
    for (int mi = 0; mi < 4; ++mi)
#pragma unroll
        for (int ni = 0; ni < 4; ++ni)
#pragma unroll
            for (int r = 0; r < 4; ++r) acc[mi][ni][r] = 0.0f;

    // precomputed per-thread load coords
    const int arow = tid >> 1;                   // wrong for 4 chunks; use f-form below

    // ---- issue loads for k0 into stage ----
    auto issue = [&](int k0, int stage) {
#pragma unroll
        for (int i = 0; i < 4; ++i) {
            int f   = tid + i * 256;
            int row = f >> 3;
            int c4  = (f & 7) * 4;
            int grow = block_row + row;
            int ok  = (grow < N_NODES);
            const float* srcp = feat + (size_t)(ok ? grow : 0) * IN_F + k0 + c4;
            uint32_t dst = as_base + (uint32_t)(stage * A_FLOATS + row * ASTRIDE + c4) * 4u;
            CP_ASYNC16_Z(dst, srcp, ok ? 16 : 0);
        }
#pragma unroll
        for (int i = 0; i < 4; ++i) {
            int f  = tid + i * 256;
            int kk = f >> 5;
            int n4 = (f & 31) * 4;
            const float* srcp = g_w + (size_t)(k0 + kk) * OUT_F + n4;
            uint32_t dst = bs_base + (uint32_t)(stage * B_FLOATS + kk * BSTRIDE + n4) * 4u;
            CP_ASYNC16(dst, srcp);
        }
        CP_COMMIT();
    };

    issue(0, 0);

    for (int k0i = 0; k0i < 8; ++k0i) {
        const int stage = k0i & 1;
        if (k0i + 1 < 8) {
            issue((k0i + 1) * 32, stage ^ 1);
            CP_WAIT1();
        } else {
            CP_WAIT0();
        }
        __syncthreads();

        const uint32_t* As_u = reinterpret_cast<const uint32_t*>(Asf + stage * A_FLOATS);
        const uint32_t* Bs_u = reinterpret_cast<const uint32_t*>(Bsf + stage * B_FLOATS);

#pragma unroll
        for (int ks = 0; ks < 4; ++ks) {
            const int kb = ks * 8;
            uint32_t a[4][4], b[4][2];
#pragma unroll
            for (int mi = 0; mi < 4; ++mi) {
                int r = wm * 64 + mi * 16 + g;
                uint32_t a0 = As_u[(r)     * ASTRIDE + kb + t4];
                uint32_t a1 = As_u[(r + 8) * ASTRIDE + kb + t4];
                uint32_t a2 = As_u[(r)     * ASTRIDE + kb + t4 + 4];
                uint32_t a3 = As_u[(r + 8) * ASTRIDE + kb + t4 + 4];
                a[mi][0] = f2tf32(__uint_as_float(a0));
                a[mi][1] = f2tf32(__uint_as_float(a1));
                a[mi][2] = f2tf32(__uint_as_float(a2));
                a[mi][3] = f2tf32(__uint_as_float(a3));
            }
#pragma unroll
            for (int ni = 0; ni < 4; ++ni) {
                int cn = wn * 32 + ni * 8 + g;
                b[ni][0] = Bs_u[(kb + t4)     * BSTRIDE + cn];   // already tf32-rounded
                b[ni][1] = Bs_u[(kb + t4 + 4) * BSTRIDE + cn];
            }
#pragma unroll
            for (int mi = 0; mi < 4; ++mi)
#pragma unroll
                for (int ni = 0; ni < 4; ++ni) {
                    asm volatile(
                        "mma.sync.aligned.m16n8k8.row.col.f32.tf32.tf32.f32 "
                        "{%0,%1,%2,%3}, {%4,%5,%6,%7}, {%8,%9}, {%0,%1,%2,%3};"
                        : "+f"(acc[mi][ni][0]), "+f"(acc[mi][ni][1]),
                          "+f"(acc[mi][ni][2]), "+f"(acc[mi][ni][3])
                        : "r"(a[mi][0]), "r"(a[mi][1]), "r"(a[mi][2]), "r"(a[mi][3]),
                          "r"(b[ni][0]), "r"(b[ni][1]));
                }
        }
        __syncthreads();
    }

    // epilogue: adjacent column pairs -> half2 stores
#pragma unroll
    for (int mi = 0; mi < 4; ++mi) {
        int r0 = block_row + wm * 64 + mi * 16 + g;
        int r1 = r0 + 8;
#pragma unroll
        for (int ni = 0; ni < 4; ++ni) {
            int col = wn * 32 + ni * 8 + 2 * t4;
            if (r0 < N_NODES) {
                __half2 h = __floats2half2_rn(acc[mi][ni][0], acc[mi][ni][1]);
                *reinterpret_cast<__half2*>(g_proj + (size_t)r0 * OUT_F + col) = h;
            }
            if (r1 < N_NODES) {
                __half2 h = __floats2half2_rn(acc[mi][ni][2], acc[mi][ni][3]);
                *reinterpret_cast<__half2*>(g_proj + (size_t)r1 * OUT_F + col) = h;
            }
        }
    }
}

// ---------------- CSR gather (fp16 rows) + in-deg norm + bias --------------
__global__ __launch_bounds__(256)
void gather_kernel(float* __restrict__ out, const float* __restrict__ bias) {
    int warp = (blockIdx.x * blockDim.x + threadIdx.x) >> 5;
    int lane = threadIdx.x & 31;
    if (warp >= N_NODES) return;

    const int start = g_start[warp];
    const int deg   = (int)g_indeg[warp];

    float4 acc = make_float4(0.f, 0.f, 0.f, 0.f);

    for (int j = 0; j < deg; j += 32) {
        int idx = j + lane;
        int s = 0; float w = 0.f;
        if (idx < deg) {
            int2 e = g_edge[start + idx];
            s = e.x;
            w = __int_as_float(e.y);
        }
        int m = min(32, deg - j);
        int t = 0;
        for (; t + 4 <= m; t += 4) {
            int   s0 = __shfl_sync(0xffffffffu, s, t);
            int   s1 = __shfl_sync(0xffffffffu, s, t + 1);
            int   s2 = __shfl_sync(0xffffffffu, s, t + 2);
            int   s3 = __shfl_sync(0xffffffffu, s, t + 3);
            float w0 = __shfl_sync(0xffffffffu, w, t);
            float w1 = __shfl_sync(0xffffffffu, w, t + 1);
            float w2 = __shfl_sync(0xffffffffu, w, t + 2);
            float w3 = __shfl_sync(0xffffffffu, w, t + 3);
            uint2 u0 = *reinterpret_cast<const uint2*>(g_proj + (size_t)s0 * OUT_F + lane * 4);
            uint2 u1 = *reinterpret_cast<const uint2*>(g_proj + (size_t)s1 * OUT_F + lane * 4);
            uint2 u2 = *reinterpret_cast<const uint2*>(g_proj + (size_t)s2 * OUT_F + lane * 4);
            uint2 u3 = *reinterpret_cast<const uint2*>(g_proj + (size_t)s3 * OUT_F + lane * 4);
            float2 a0 = __half22float2(*reinterpret_cast<__half2*>(&u0.x));
            float2 b0 = __half22float2(*reinterpret_cast<__half2*>(&u0.y));
            float2 a1 = __half22float2(*reinterpret_cast<__half2*>(&u1.x));
            float2 b1 = __half22float2(*reinterpret_cast<__half2*>(&u1.y));
            float2 a2 = __half22float2(*reinterpret_cast<__half2*>(&u2.x));
            float2 b2 = __half22float2(*reinterpret_cast<__half2*>(&u2.y));
            float2 a3 = __half22float2(*reinterpret_cast<__half2*>(&u3.x));
            float2 b3 = __half22float2(*reinterpret_cast<__half2*>(&u3.y));
            acc.x = fmaf(a0.x, w0, acc.x); acc.y = fmaf(a0.y, w0, acc.y);
            acc.z = fmaf(b0.x, w0, acc.z); acc.w = fmaf(b0.y, w0, acc.w);
            acc.x = fmaf(a1.x, w1, acc.x); acc.y = fmaf(a1.y, w1, acc.y);
            acc.z = fmaf(b1.x, w1, acc.z); acc.w = fmaf(b1.y, w1, acc.w);
            acc.x = fmaf(a2.x, w2, acc.x); acc.y = fmaf(a2.y, w2, acc.y);
            acc.z = fmaf(b2.x, w2, acc.z); acc.w = fmaf(b2.y, w2, acc.w);
            acc.x = fmaf(a3.x, w3, acc.x); acc.y = fmaf(a3.y, w3, acc.y);
            acc.z = fmaf(b3.x, w3, acc.z); acc.w = fmaf(b3.y, w3, acc.w);
        }
        for (; t < m; ++t) {
            int   ss = __shfl_sync(0xffffffffu, s, t);
            float ww = __shfl_sync(0xffffffffu, w, t);
            uint2 u = *reinterpret_cast<const uint2*>(g_proj + (size_t)ss * OUT_F + lane * 4);
            float2 a = __half22float2(*reinterpret_cast<__half2*>(&u.x));
            float2 b = __half22float2(*reinterpret_cast<__half2*>(&u.y));
            acc.x = fmaf(a.x, ww, acc.x); acc.y = fmaf(a.y, ww, acc.y);
            acc.z = fmaf(b.x, ww, acc.z); acc.w = fmaf(b.y, ww, acc.w);
        }
    }

    const float si = g_inv_in[warp];
    float4 b = reinterpret_cast<const float4*>(bias)[lane];
    float4 o;
    o.x = fmaf(acc.x, si, b.x);
    o.y = fmaf(acc.y, si, b.y);
    o.z = fmaf(acc.z, si, b.z);
    o.w = fmaf(acc.w, si, b.w);
    *reinterpret_cast<float4*>(out + (size_t)warp * OUT_F + lane * 4) = o;
}

// ---------------- launch ----------------------------------------------------
extern "C" void kernel_launch(void* const* d_in, const int* in_sizes, int n_in,
                              void* d_out, int out_size) {
    const float* feat      = (const float*)d_in[0];
    const int*   src       = (const int*)  d_in[1];
    const int*   dst       = (const int*)  d_in[2];
    const float* ew        = (const float*)d_in[3];
    const float* weight    = (const float*)d_in[4];
    const float* bias      = (const float*)d_in[5];
    const float* mask_real = (const float*)d_in[6];
    float* out = (float*)d_out;

    cudaFuncSetAttribute(gemm_mma_kernel,
                         cudaFuncAttributeMaxDynamicSharedMemorySize,
                         SMEM_FLOATS * 4);

    const int nscan = (N_NODES + 255) / 256;   // 391

    prep_kernel<<<nscan, 256>>>(weight, mask_real);
    count_kernel<<<(E_EDGES / 2 + 255) / 256, 256>>>((const int2*)src, (const int2*)dst);
    scanA_kernel<<<nscan, 256>>>();
    scanC_kernel<<<nscan, 256>>>();
    scatter_kernel<<<(E_EDGES + 255) / 256, 256>>>(src, dst, ew);
    gemm_mma_kernel<<<(N_NODES + 127) / 128, 256, SMEM_FLOATS * 4>>>(feat);
    gather_kernel<<<(N_NODES * 32 + 255) / 256, 256>>>(out, bias);
}